// round 1
// baseline (speedup 1.0000x reference)
#include <cuda_runtime.h>

namespace {

constexpr int W_IMG = 192;
constexpr int HW    = 192 * 192;        // 36864
constexpr int CHW   = 192 * HW;         // 7077888
constexpr int QP    = 34;               // Q/K smem row pad (floats)
constexpr int SP    = 66;               // S (scores) row pad
constexpr int VP    = 68;               // Vt row pad

__device__ __forceinline__ unsigned long long fma2(unsigned long long a,
                                                   unsigned long long b,
                                                   unsigned long long c) {
  unsigned long long d;
  asm("fma.rn.f32x2 %0, %1, %2, %3;" : "=l"(d) : "l"(a), "l"(b), "l"(c));
  return d;
}

__device__ __forceinline__ float lo_plus_hi(unsigned long long a) {
  float x, y;
  asm("mov.b64 {%0, %1}, %2;" : "=f"(x), "=f"(y) : "l"(a));
  return x + y;
}

}  // namespace

__global__ __launch_bounds__(128, 4) void winattn_kernel(
    const float* __restrict__ kv, const float* __restrict__ q,
    const float* __restrict__ mask, float* __restrict__ out) {
  __shared__ float sQ[64 * QP];    // [n][ci], pad 34
  __shared__ float sK[64 * QP];    // row-permuted: phys row = (n&7)*8 + (n>>3)
  __shared__ float sVt[32 * VP];   // [ci][n] transposed, phys row = (ci&3)*8 + (ci>>2)
  __shared__ float sS[64 * SP];    // scores / probs, pad 66
  __shared__ float sInv[64];       // 1/rowsum

  const int tid = threadIdx.x;
  int blk = blockIdx.x;
  const int d = blk % 6; blk /= 6;
  const int b = blk % 8; blk /= 8;
  const int v = blk % 24;
  const int u = blk / 24;

  const int base = b * CHW + d * 32 * HW + (u * 8) * W_IMG + v * 8;
  const float* __restrict__ qg = q + base;
  const float* __restrict__ kg = kv + base;
  const float* __restrict__ vg = kv + 8 * CHW + base;

  // ---------------- load Q, K, V tiles (512 float4 each) ----------------
#pragma unroll
  for (int it = 0; it < 4; it++) {
    const int p  = it * 128 + tid;   // quad id 0..511
    const int ci = p >> 4;           // 0..31
    const int h  = (p >> 1) & 7;     // 0..7
    const int wq = p & 1;            // 0..1
    const int goff = ci * HW + h * W_IMG + wq * 4;
    const int n0 = h * 8 + wq * 4;   // window position of first of 4

    float4 a = *(const float4*)(qg + goff);
    sQ[(n0 + 0) * QP + ci] = a.x;
    sQ[(n0 + 1) * QP + ci] = a.y;
    sQ[(n0 + 2) * QP + ci] = a.z;
    sQ[(n0 + 3) * QP + ci] = a.w;

    a = *(const float4*)(kg + goff);
#pragma unroll
    for (int kq = 0; kq < 4; kq++) {
      const int n = n0 + kq;
      const float val = (kq == 0) ? a.x : (kq == 1) ? a.y : (kq == 2) ? a.z : a.w;
      sK[(((n & 7) * 8) + (n >> 3)) * QP + ci] = val;
    }

    a = *(const float4*)(vg + goff);
    const int pc = (ci & 3) * 8 + (ci >> 2);
    *(float4*)(&sVt[pc * VP + n0]) = a;
  }

  // ---------------- mask -> sS (coalesced) ----------------
  const float* __restrict__ mg = mask + (u * 24 + v) * 4096;
#pragma unroll
  for (int it = 0; it < 16; it++) {
    const int p = it * 128 + tid;    // float2 id 0..2047
    const float2 m2 = *(const float2*)(mg + p * 2);
    *(float2*)(&sS[(p >> 5) * SP + (p & 31) * 2]) = m2;
  }
  __syncthreads();

  // ---------------- S = Q K^T * scale + mask ----------------
  {
    const int tr = tid >> 3;   // 0..15 -> 4-row tile
    const int tc = tid & 7;    // 0..7  -> 8-col tile
    const int r0 = tr * 4;
    const int c0 = tc * 8;
    unsigned long long acc[4][8];
#pragma unroll
    for (int i = 0; i < 4; i++)
#pragma unroll
      for (int j = 0; j < 8; j++) acc[i][j] = 0ull;

#pragma unroll 4
    for (int kk = 0; kk < 16; kk++) {   // ci pairs
      unsigned long long q2[4], k2[8];
#pragma unroll
      for (int i = 0; i < 4; i++)
        q2[i] = *(const unsigned long long*)(&sQ[(r0 + i) * QP + kk * 2]);
#pragma unroll
      for (int j = 0; j < 8; j++)       // K col c0+j -> phys row j*8+tc
        k2[j] = *(const unsigned long long*)(&sK[(j * 8 + tc) * QP + kk * 2]);
#pragma unroll
      for (int i = 0; i < 4; i++)
#pragma unroll
        for (int j = 0; j < 8; j++) acc[i][j] = fma2(q2[i], k2[j], acc[i][j]);
    }

    const float scale = 0.1767766952966369f;  // 1/sqrt(32)
#pragma unroll
    for (int i = 0; i < 4; i++) {
      float* row = &sS[(r0 + i) * SP + c0];
#pragma unroll
      for (int j = 0; j < 8; j++)
        row[j] = fmaf(lo_plus_hi(acc[i][j]), scale, row[j]);
    }
  }
  __syncthreads();

  // ---------------- row softmax (unnormalized exp; keep 1/sum) ----------------
  {
    const int r = tid >> 1;
    const int off = (tid & 1) * 32;
    float* row = &sS[r * SP + off];
    float mx = -1e30f;
#pragma unroll
    for (int k = 0; k < 32; k++) mx = fmaxf(mx, row[k]);
    mx = fmaxf(mx, __shfl_xor_sync(0xffffffffu, mx, 1));
    float sum = 0.f;
#pragma unroll
    for (int k = 0; k < 32; k++) {
      const float e = __expf(row[k] - mx);
      row[k] = e;
      sum += e;
    }
    sum += __shfl_xor_sync(0xffffffffu, sum, 1);
    if ((tid & 1) == 0) sInv[r] = 1.0f / sum;
  }
  __syncthreads();

  // ---------------- O = P V  (written into sQ, then coalesced store) ----------------
  {
    const int tr = tid >> 3;   // 0..15 -> 4-row tile
    const int tc = tid & 7;    // 0..7  -> 4-ci tile (c0 = 4*tc)
    const int r0 = tr * 4;
    unsigned long long acc[4][4];
#pragma unroll
    for (int i = 0; i < 4; i++)
#pragma unroll
      for (int j = 0; j < 4; j++) acc[i][j] = 0ull;

#pragma unroll 4
    for (int nn = 0; nn < 32; nn++) {   // key-position pairs
      unsigned long long p2[4], v2[4];
#pragma unroll
      for (int i = 0; i < 4; i++)
        p2[i] = *(const unsigned long long*)(&sS[(r0 + i) * SP + nn * 2]);
#pragma unroll
      for (int j = 0; j < 4; j++)       // ci = 4*tc + j -> phys row j*8+tc
        v2[j] = *(const unsigned long long*)(&sVt[(j * 8 + tc) * VP + nn * 2]);
#pragma unroll
      for (int i = 0; i < 4; i++)
#pragma unroll
        for (int j = 0; j < 4; j++) acc[i][j] = fma2(p2[i], v2[j], acc[i][j]);
    }

#pragma unroll
    for (int i = 0; i < 4; i++) {
      const float inv = sInv[r0 + i];
#pragma unroll
      for (int j = 0; j < 4; j++)
        sQ[(r0 + i) * QP + tc * 4 + j] = lo_plus_hi(acc[i][j]) * inv;
    }
  }
  __syncthreads();

  // ---------------- coalesced global store ----------------
  float* __restrict__ og = out + base;
#pragma unroll
  for (int it = 0; it < 4; it++) {
    const int p  = it * 128 + tid;
    const int ci = p >> 4;
    const int h  = (p >> 1) & 7;
    const int wq = p & 1;
    const int n0 = h * 8 + wq * 4;
    float4 a;
    a.x = sQ[(n0 + 0) * QP + ci];
    a.y = sQ[(n0 + 1) * QP + ci];
    a.z = sQ[(n0 + 2) * QP + ci];
    a.w = sQ[(n0 + 3) * QP + ci];
    *(float4*)(og + ci * HW + h * W_IMG + wq * 4) = a;
  }
}

extern "C" void kernel_launch(void* const* d_in, const int* in_sizes, int n_in,
                              void* d_out, int out_size) {
  // Identify inputs by size for robustness:
  //   kv   : 2*8*192^3 = 113246208
  //   q    :   8*192^3 =  56623104
  //   mask : 576*64*64 =   2359296
  const float* kv = nullptr;
  const float* q = nullptr;
  const float* mask = nullptr;
  for (int i = 0; i < n_in; i++) {
    if (in_sizes[i] == 113246208) kv = (const float*)d_in[i];
    else if (in_sizes[i] == 56623104) q = (const float*)d_in[i];
    else if (in_sizes[i] == 2359296) mask = (const float*)d_in[i];
  }
  // Fallback to metadata order if sizes were unexpected
  if (!kv)   kv   = (const float*)d_in[0];
  if (!q)    q    = (const float*)d_in[1];
  if (!mask) mask = (const float*)d_in[2];

  float* out = (float*)d_out;
  winattn_kernel<<<27648, 128>>>(kv, q, mask, out);
}

// round 2
// speedup vs baseline: 1.0549x; 1.0549x over previous
#include <cuda_runtime.h>

namespace {

constexpr int W_IMG = 192;
constexpr int HW    = 192 * 192;        // 36864
constexpr int CHW   = 192 * HW;         // 7077888
constexpr int QP    = 34;               // Q/K smem row pad (floats)
constexpr int SP    = 66;               // S (scores) row pad
constexpr int VP    = 68;               // Vt row pad

__device__ __forceinline__ unsigned long long fma2(unsigned long long a,
                                                   unsigned long long b,
                                                   unsigned long long c) {
  unsigned long long d;
  asm("fma.rn.f32x2 %0, %1, %2, %3;" : "=l"(d) : "l"(a), "l"(b), "l"(c));
  return d;
}

__device__ __forceinline__ float lo_plus_hi(unsigned long long a) {
  float x, y;
  asm("mov.b64 {%0, %1}, %2;" : "=f"(x), "=f"(y) : "l"(a));
  return x + y;
}

}  // namespace

__global__ __launch_bounds__(128, 4) void winattn_kernel(
    const float* __restrict__ kv, const float* __restrict__ q,
    const float* __restrict__ mask, float* __restrict__ out) {
  __shared__ float sQ[64 * QP];    // [n][ci], pad 34
  __shared__ float sK[64 * QP];    // row-permuted: phys row = (n&7)*8 + (n>>3)
  __shared__ float sVt[32 * VP];   // [ci][n] transposed, phys row = (ci&3)*8 + (ci>>2)
  __shared__ float sS[64 * SP];    // scores / probs, pad 66
  __shared__ float sInv[64];       // 1/rowsum

  const int tid = threadIdx.x;
  int blk = blockIdx.x;
  const int d = blk % 6; blk /= 6;
  const int b = blk % 8; blk /= 8;
  const int v = blk % 24;
  const int u = blk / 24;

  const int base = b * CHW + d * 32 * HW + (u * 8) * W_IMG + v * 8;
  const float* __restrict__ qg = q + base;
  const float* __restrict__ kg = kv + base;
  const float* __restrict__ vg = kv + 8 * CHW + base;

  // ---------------- load Q, K, V tiles (512 float4 each) ----------------
#pragma unroll
  for (int it = 0; it < 4; it++) {
    const int p  = it * 128 + tid;   // quad id 0..511
    const int ci = p >> 4;           // 0..31
    const int h  = (p >> 1) & 7;     // 0..7
    const int wq = p & 1;            // 0..1
    const int goff = ci * HW + h * W_IMG + wq * 4;
    const int n0 = h * 8 + wq * 4;   // window position of first of 4

    float4 a = *(const float4*)(qg + goff);
    sQ[(n0 + 0) * QP + ci] = a.x;
    sQ[(n0 + 1) * QP + ci] = a.y;
    sQ[(n0 + 2) * QP + ci] = a.z;
    sQ[(n0 + 3) * QP + ci] = a.w;

    a = *(const float4*)(kg + goff);
#pragma unroll
    for (int kq = 0; kq < 4; kq++) {
      const int n = n0 + kq;
      const float val = (kq == 0) ? a.x : (kq == 1) ? a.y : (kq == 2) ? a.z : a.w;
      sK[(((n & 7) * 8) + (n >> 3)) * QP + ci] = val;
    }

    a = *(const float4*)(vg + goff);
    const int pc = (ci & 3) * 8 + (ci >> 2);
    *(float4*)(&sVt[pc * VP + n0]) = a;
  }

  // ---------------- mask -> sS (coalesced) ----------------
  const float* __restrict__ mg = mask + (u * 24 + v) * 4096;
#pragma unroll
  for (int it = 0; it < 16; it++) {
    const int p = it * 128 + tid;    // float2 id 0..2047
    const float2 m2 = *(const float2*)(mg + p * 2);
    *(float2*)(&sS[(p >> 5) * SP + (p & 31) * 2]) = m2;
  }
  __syncthreads();

  // ---------------- S = Q K^T * scale + mask ----------------
  {
    const int tr = tid >> 3;   // 0..15 -> 4-row tile
    const int tc = tid & 7;    // 0..7  -> 8-col tile
    const int r0 = tr * 4;
    const int c0 = tc * 8;
    unsigned long long acc[4][8];
#pragma unroll
    for (int i = 0; i < 4; i++)
#pragma unroll
      for (int j = 0; j < 8; j++) acc[i][j] = 0ull;

#pragma unroll 4
    for (int kk = 0; kk < 16; kk++) {   // ci pairs
      unsigned long long q2[4], k2[8];
#pragma unroll
      for (int i = 0; i < 4; i++)
        q2[i] = *(const unsigned long long*)(&sQ[(r0 + i) * QP + kk * 2]);
#pragma unroll
      for (int j = 0; j < 8; j++)       // K col c0+j -> phys row j*8+tc
        k2[j] = *(const unsigned long long*)(&sK[(j * 8 + tc) * QP + kk * 2]);
#pragma unroll
      for (int i = 0; i < 4; i++)
#pragma unroll
        for (int j = 0; j < 8; j++) acc[i][j] = fma2(q2[i], k2[j], acc[i][j]);
    }

    const float scale = 0.1767766952966369f;  // 1/sqrt(32)
#pragma unroll
    for (int i = 0; i < 4; i++) {
      float* row = &sS[(r0 + i) * SP + c0];
#pragma unroll
      for (int j = 0; j < 8; j++)
        row[j] = fmaf(lo_plus_hi(acc[i][j]), scale, row[j]);
    }
  }
  __syncthreads();

  // ---------------- row softmax (unnormalized exp; keep 1/sum) ----------------
  {
    const int r = tid >> 1;
    const int off = (tid & 1) * 32;
    float* row = &sS[r * SP + off];
    float mx = -1e30f;
#pragma unroll
    for (int k = 0; k < 32; k++) mx = fmaxf(mx, row[k]);
    mx = fmaxf(mx, __shfl_xor_sync(0xffffffffu, mx, 1));
    float sum = 0.f;
#pragma unroll
    for (int k = 0; k < 32; k++) {
      const float e = __expf(row[k] - mx);
      row[k] = e;
      sum += e;
    }
    sum += __shfl_xor_sync(0xffffffffu, sum, 1);
    if ((tid & 1) == 0) sInv[r] = 1.0f / sum;
  }
  __syncthreads();

  // ---------------- O = P V  (written into sQ, then coalesced store) ----------------
  {
    const int tr = tid >> 3;   // 0..15 -> 4-row tile
    const int tc = tid & 7;    // 0..7  -> 4-ci tile (c0 = 4*tc)
    const int r0 = tr * 4;
    unsigned long long acc[4][4];
#pragma unroll
    for (int i = 0; i < 4; i++)
#pragma unroll
      for (int j = 0; j < 4; j++) acc[i][j] = 0ull;

#pragma unroll 4
    for (int nn = 0; nn < 32; nn++) {   // key-position pairs
      unsigned long long p2[4], v2[4];
#pragma unroll
      for (int i = 0; i < 4; i++)
        p2[i] = *(const unsigned long long*)(&sS[(r0 + i) * SP + nn * 2]);
#pragma unroll
      for (int j = 0; j < 4; j++)       // ci = 4*tc + j -> phys row j*8+tc
        v2[j] = *(const unsigned long long*)(&sVt[(j * 8 + tc) * VP + nn * 2]);
#pragma unroll
      for (int i = 0; i < 4; i++)
#pragma unroll
        for (int j = 0; j < 4; j++) acc[i][j] = fma2(p2[i], v2[j], acc[i][j]);
    }

#pragma unroll
    for (int i = 0; i < 4; i++) {
      const float inv = sInv[r0 + i];
#pragma unroll
      for (int j = 0; j < 4; j++)
        sQ[(r0 + i) * QP + tc * 4 + j] = lo_plus_hi(acc[i][j]) * inv;
    }
  }
  __syncthreads();

  // ---------------- coalesced global store ----------------
  float* __restrict__ og = out + base;
#pragma unroll
  for (int it = 0; it < 4; it++) {
    const int p  = it * 128 + tid;
    const int ci = p >> 4;
    const int h  = (p >> 1) & 7;
    const int wq = p & 1;
    const int n0 = h * 8 + wq * 4;
    float4 a;
    a.x = sQ[(n0 + 0) * QP + ci];
    a.y = sQ[(n0 + 1) * QP + ci];
    a.z = sQ[(n0 + 2) * QP + ci];
    a.w = sQ[(n0 + 3) * QP + ci];
    *(float4*)(og + ci * HW + h * W_IMG + wq * 4) = a;
  }
}

extern "C" void kernel_launch(void* const* d_in, const int* in_sizes, int n_in,
                              void* d_out, int out_size) {
  // Identify inputs by size for robustness:
  //   kv   : 2*8*192^3 = 113246208
  //   q    :   8*192^3 =  56623104
  //   mask : 576*64*64 =   2359296
  const float* kv = nullptr;
  const float* q = nullptr;
  const float* mask = nullptr;
  for (int i = 0; i < n_in; i++) {
    if (in_sizes[i] == 113246208) kv = (const float*)d_in[i];
    else if (in_sizes[i] == 56623104) q = (const float*)d_in[i];
    else if (in_sizes[i] == 2359296) mask = (const float*)d_in[i];
  }
  // Fallback to metadata order if sizes were unexpected
  if (!kv)   kv   = (const float*)d_in[0];
  if (!q)    q    = (const float*)d_in[1];
  if (!mask) mask = (const float*)d_in[2];

  float* out = (float*)d_out;
  winattn_kernel<<<27648, 128>>>(kv, q, mask, out);
}

// round 5
// speedup vs baseline: 2.4523x; 2.3248x over previous
#include <cuda_runtime.h>
#include <cuda_bf16.h>
#include <cstdint>

namespace {

constexpr int   HW    = 36864;        // 192*192
constexpr int   CHW   = 7077888;      // 192*HW
constexpr int   VOFF  = 56623104;     // V plane offset inside kv (8*CHW)
constexpr float SCALE = 0.17677669529663687f;  // 1/sqrt(32)

// smem word offsets (uint32 units)
constexpr int QHI = 0;        // 64 rows x 20 words
constexpr int QLO = 1280;
constexpr int KHI = 2560;
constexpr int KLO = 3840;
constexpr int VHI = 5120;     // 32 rows x 36 words
constexpr int VLO = 6272;
constexpr int SMW = 7424;     // total words (29696 B)

__device__ __forceinline__ uint32_t pack2(float lo, float hi) {
  // result: low 16 bits = bf16(lo), high 16 bits = bf16(hi)
  uint32_t r;
  asm("cvt.rn.bf16x2.f32 %0, %1, %2;" : "=r"(r) : "f"(hi), "f"(lo));
  return r;
}
__device__ __forceinline__ float bfv(float f) {
  return __bfloat162float(__float2bfloat16_rn(f));
}
__device__ __forceinline__ void mma_bf16(float* c, const uint32_t* a,
                                         uint32_t b0, uint32_t b1) {
  asm volatile(
      "mma.sync.aligned.m16n8k16.row.col.f32.bf16.bf16.f32 "
      "{%0,%1,%2,%3}, {%4,%5,%6,%7}, {%8,%9}, {%0,%1,%2,%3};"
      : "+f"(c[0]), "+f"(c[1]), "+f"(c[2]), "+f"(c[3])
      : "r"(a[0]), "r"(a[1]), "r"(a[2]), "r"(a[3]), "r"(b0), "r"(b1));
}
// Q/K tile addressing: row-stride 20 words, word index XOR-swizzled by row bits.
// Fragment reads (rows 8j+g, word 8ks+t) are conflict-free; staging stores 2-way.
__device__ __forceinline__ int qkw(int r, int w) {
  return r * 20 + (w ^ (((r >> 3) & 3) << 2));
}
__device__ __forceinline__ float felem(float4 a, int j) {
  return (j == 0) ? a.x : (j == 1) ? a.y : (j == 2) ? a.z : a.w;
}

}  // namespace

__global__ __launch_bounds__(128, 4) void winattn_mma(
    const float* __restrict__ kv, const float* __restrict__ q,
    const float* __restrict__ mask, float* __restrict__ out) {
  __shared__ __align__(16) uint32_t sm[SMW];

  const int tid = threadIdx.x;
  const int wid = tid >> 5;
  const int lid = tid & 31;

  // block decode: 48 consecutive CTAs (8 b x 6 d) share one mask window (L2 reuse)
  const int blk = blockIdx.x;
  const int win = blk / 48;      // 0..575
  const int rem = blk % 48;
  const int b = rem / 6;
  const int d = rem % 6;
  const int u = win / 24;
  const int v = win % 24;

  const int base = b * CHW + d * 32 * HW + (u * 8) * 192 + v * 8;
  const float* __restrict__ qg = q + base;
  const float* __restrict__ kg = kv + base;
  const float* __restrict__ vg = kv + VOFF + base;
  float* __restrict__ og = out + base;

  // ================= stage Q, K (hi/lo split, [row=n][word=ci/2]) =================
#pragma unroll
  for (int it = 0; it < 2; it++) {
    const int p  = it * 128 + tid;       // 0..255
    const int cw = p >> 4;               // word index = ci/2 (0..15)
    const int h  = (p >> 1) & 7;
    const int wq = p & 1;
    const int n0 = h * 8 + wq * 4;
    const int go = cw * 2 * HW + h * 192 + wq * 4;

    float4 a0 = *(const float4*)(qg + go);
    float4 a1 = *(const float4*)(qg + go + HW);
#pragma unroll
    for (int j = 0; j < 4; j++) {
      const float f0 = felem(a0, j), f1 = felem(a1, j);
      const int w = qkw(n0 + j, cw);
      sm[QHI + w] = pack2(f0, f1);
      sm[QLO + w] = pack2(f0 - bfv(f0), f1 - bfv(f1));
    }
    a0 = *(const float4*)(kg + go);
    a1 = *(const float4*)(kg + go + HW);
#pragma unroll
    for (int j = 0; j < 4; j++) {
      const float f0 = felem(a0, j), f1 = felem(a1, j);
      const int w = qkw(n0 + j, cw);
      sm[KHI + w] = pack2(f0, f1);
      sm[KLO + w] = pack2(f0 - bfv(f0), f1 - bfv(f1));
    }
  }
  // ================= stage V transposed: [row=ci][word=key/2], stride 36 ========
#pragma unroll
  for (int it = 0; it < 4; it++) {
    const int p  = it * 128 + tid;       // 0..511
    const int ci = p >> 4;
    const int h  = (p >> 1) & 7;
    const int wq = p & 1;
    const int n0 = h * 8 + wq * 4;
    const float4 a = *(const float4*)(vg + ci * HW + h * 192 + wq * 4);
    uint2 hp, lp;
    hp.x = pack2(a.x, a.y);
    hp.y = pack2(a.z, a.w);
    lp.x = pack2(a.x - bfv(a.x), a.y - bfv(a.y));
    lp.y = pack2(a.z - bfv(a.z), a.w - bfv(a.w));
    *(uint2*)&sm[VHI + ci * 36 + (n0 >> 1)] = hp;
    *(uint2*)&sm[VLO + ci * 36 + (n0 >> 1)] = lp;
  }
  __syncthreads();

  // ================= QK^T : warp owns rows m0..m0+15 ===========================
  const int g  = lid >> 2;   // 0..7
  const int t  = lid & 3;    // 0..3
  const int m0 = wid * 16;

  uint32_t aqh[2][4], aql[2][4];
#pragma unroll
  for (int ks = 0; ks < 2; ks++) {
    aqh[ks][0] = sm[QHI + qkw(m0 + g,     ks * 8 + t)];
    aqh[ks][1] = sm[QHI + qkw(m0 + g + 8, ks * 8 + t)];
    aqh[ks][2] = sm[QHI + qkw(m0 + g,     ks * 8 + 4 + t)];
    aqh[ks][3] = sm[QHI + qkw(m0 + g + 8, ks * 8 + 4 + t)];
    aql[ks][0] = sm[QLO + qkw(m0 + g,     ks * 8 + t)];
    aql[ks][1] = sm[QLO + qkw(m0 + g + 8, ks * 8 + t)];
    aql[ks][2] = sm[QLO + qkw(m0 + g,     ks * 8 + 4 + t)];
    aql[ks][3] = sm[QLO + qkw(m0 + g + 8, ks * 8 + 4 + t)];
  }

  float c[8][4];
#pragma unroll
  for (int j = 0; j < 8; j++)
#pragma unroll
    for (int i = 0; i < 4; i++) c[j][i] = 0.f;

#pragma unroll
  for (int j = 0; j < 8; j++) {          // n-tile: cols 8j..8j+7
    const int rb = j * 8 + g;
#pragma unroll
    for (int ks = 0; ks < 2; ks++) {
      const uint32_t bh0 = sm[KHI + qkw(rb, ks * 8 + t)];
      const uint32_t bh1 = sm[KHI + qkw(rb, ks * 8 + 4 + t)];
      const uint32_t bl0 = sm[KLO + qkw(rb, ks * 8 + t)];
      const uint32_t bl1 = sm[KLO + qkw(rb, ks * 8 + 4 + t)];
      mma_bf16(c[j], aqh[ks], bh0, bh1);
      mma_bf16(c[j], aqh[ks], bl0, bl1);
      mma_bf16(c[j], aql[ks], bh0, bh1);
    }
  }

  // ================= softmax (rows m0+g and m0+g+8, quad-local) =================
  const float* __restrict__ mrow = mask + win * 4096 + (m0 + g) * 64 + 2 * t;
  float sum0 = 0.f, sum1 = 0.f;
#pragma unroll
  for (int j = 0; j < 8; j++) {
    const float2 mv0 = *(const float2*)(mrow + j * 8);
    const float2 mv1 = *(const float2*)(mrow + 512 + j * 8);
    float e;
    e = __expf(fmaf(c[j][0], SCALE, mv0.x)); c[j][0] = e; sum0 += e;
    e = __expf(fmaf(c[j][1], SCALE, mv0.y)); c[j][1] = e; sum0 += e;
    e = __expf(fmaf(c[j][2], SCALE, mv1.x)); c[j][2] = e; sum1 += e;
    e = __expf(fmaf(c[j][3], SCALE, mv1.y)); c[j][3] = e; sum1 += e;
  }
  sum0 += __shfl_xor_sync(0xffffffffu, sum0, 1);
  sum0 += __shfl_xor_sync(0xffffffffu, sum0, 2);
  sum1 += __shfl_xor_sync(0xffffffffu, sum1, 1);
  sum1 += __shfl_xor_sync(0xffffffffu, sum1, 2);
  const float inv0 = 1.0f / sum0;
  const float inv1 = 1.0f / sum1;

  // P fragments (S accumulator layout == PV A-fragment layout), hi/lo split
  uint32_t aph[4][4], apl[4][4];
#pragma unroll
  for (int ks = 0; ks < 4; ks++) {
    const float* p0 = c[2 * ks];
    const float* p1 = c[2 * ks + 1];
    aph[ks][0] = pack2(p0[0], p0[1]);
    aph[ks][1] = pack2(p0[2], p0[3]);
    aph[ks][2] = pack2(p1[0], p1[1]);
    aph[ks][3] = pack2(p1[2], p1[3]);
    apl[ks][0] = pack2(p0[0] - bfv(p0[0]), p0[1] - bfv(p0[1]));
    apl[ks][1] = pack2(p0[2] - bfv(p0[2]), p0[3] - bfv(p0[3]));
    apl[ks][2] = pack2(p1[0] - bfv(p1[0]), p1[1] - bfv(p1[1]));
    apl[ks][3] = pack2(p1[2] - bfv(p1[2]), p1[3] - bfv(p1[3]));
  }
  __syncthreads();   // all warps done reading Q/K smem before O staging reuses it

  // ================= O = P V =====================================================
  float o[4][4];
#pragma unroll
  for (int jn = 0; jn < 4; jn++)
#pragma unroll
    for (int i = 0; i < 4; i++) o[jn][i] = 0.f;

#pragma unroll
  for (int jn = 0; jn < 4; jn++) {       // channel tile 8jn..8jn+7
    const int rv = (jn * 8 + g) * 36;
#pragma unroll
    for (int ks = 0; ks < 4; ks++) {     // key step 16ks..16ks+15
      const uint32_t bh0 = sm[VHI + rv + ks * 8 + t];
      const uint32_t bh1 = sm[VHI + rv + ks * 8 + 4 + t];
      const uint32_t bl0 = sm[VLO + rv + ks * 8 + t];
      const uint32_t bl1 = sm[VLO + rv + ks * 8 + 4 + t];
      mma_bf16(o[jn], aph[ks], bh0, bh1);
      mma_bf16(o[jn], aph[ks], bl0, bl1);
      mma_bf16(o[jn], apl[ks], bh0, bh1);
    }
  }

  // stage O: [ch][n] stride 68 floats (conflict-free writes and float4 reads)
  float* __restrict__ sO = (float*)sm;
#pragma unroll
  for (int jn = 0; jn < 4; jn++) {
    const int ch = jn * 8 + 2 * t;
    sO[ch * 68 + m0 + g]           = o[jn][0] * inv0;
    sO[(ch + 1) * 68 + m0 + g]     = o[jn][1] * inv0;
    sO[ch * 68 + m0 + g + 8]       = o[jn][2] * inv1;
    sO[(ch + 1) * 68 + m0 + g + 8] = o[jn][3] * inv1;
  }
  __syncthreads();

  // ================= coalesced global store ======================================
#pragma unroll
  for (int it = 0; it < 4; it++) {
    const int p  = it * 128 + tid;
    const int ci = p >> 4;
    const int h  = (p >> 1) & 7;
    const int wq = p & 1;
    const int n0 = h * 8 + wq * 4;
    const float4 a = *(const float4*)&sO[ci * 68 + n0];
    *(float4*)(og + ci * HW + h * 192 + wq * 4) = a;
  }
}

extern "C" void kernel_launch(void* const* d_in, const int* in_sizes, int n_in,
                              void* d_out, int out_size) {
  const float* kv = nullptr;
  const float* q = nullptr;
  const float* mask = nullptr;
  for (int i = 0; i < n_in; i++) {
    if (in_sizes[i] == 113246208) kv = (const float*)d_in[i];
    else if (in_sizes[i] == 56623104) q = (const float*)d_in[i];
    else if (in_sizes[i] == 2359296) mask = (const float*)d_in[i];
  }
  if (!kv)   kv   = (const float*)d_in[0];
  if (!q)    q    = (const float*)d_in[1];
  if (!mask) mask = (const float*)d_in[2];
  winattn_mma<<<27648, 128>>>(kv, q, mask, (float*)d_out);
}